// round 15
// baseline (speedup 1.0000x reference)
#include <cuda_runtime.h>

#define B_    8
#define C_    20
#define H_    512
#define W_    512
#define SH_   32
#define SW_   32
#define S_    1024
#define CELL_ 16
#define HW_   (H_*W_)
#define HW4   (HW_/4)
#define W4    (W_/4)
#define PSTR  260
#define PSTRQ 264            // Q staging stride (floats): 66 16B-chunks
#define EPSV  1e-8f

typedef unsigned long long u64;

// Packed fp32x2 helpers (SASS FFMA2 — PTX-only)
__device__ __forceinline__ u64 pkdup(float s) {
    u64 r; asm("mov.b64 %0,{%1,%1};" : "=l"(r) : "f"(s)); return r;
}
__device__ __forceinline__ void upk2(u64 v, float& lo, float& hi) {
    asm("mov.b64 {%0,%1},%2;" : "=f"(lo), "=f"(hi) : "l"(v));
}
__device__ __forceinline__ u64 fma2(u64 a, u64 b, u64 c) {
    u64 d; asm("fma.rn.f32x2 %0,%1,%2,%3;" : "=l"(d) : "l"(a), "l"(b), "l"(c));
    return d;
}

__device__ float g_seeds[B_][S_][C_];          // iteration-0 seeds (means)
__device__ float g_numerB[3][B_][S_][C_];      // per-iteration accumulators
__device__ float g_denomB[3][B_][S_];

__constant__ int c_dy[9] = {-1,-1,-1, 0,0,0, 1,1,1};
__constant__ int c_dx[9] = {-1, 0, 1,-1,0,1,-1,0,1};

// ---------------------------------------------------------------------------
// K0: seed init = 16x16 mean pool per (b, cell, c); zero ALL 3 accumulator
// buffers (seed division is fused into k_main's seed loader).
// ---------------------------------------------------------------------------
__global__ void __launch_bounds__(256) k_init(const float* __restrict__ x)
{
    __shared__ __align__(16) float sX[C_][PSTR];
    const int b  = blockIdx.z, cy = blockIdx.y, cx = blockIdx.x;
    const int tid = threadIdx.x;
    const int ty = tid >> 4, tx = tid & 15;
    const int sidx = cy * SW_ + cx;

    if (tid < 63) {
        const int buf = tid / 21, c = tid % 21;
        if (c < 20) g_numerB[buf][b][sidx][c] = 0.f;
        else        g_denomB[buf][b][sidx]    = 0.f;
    }

    const float* xp = x + (size_t)b * C_ * HW_
                        + (size_t)(cy * CELL_ + ty) * W_ + (cx * CELL_ + tx);
#pragma unroll
    for (int c = 0; c < C_; c++) sX[c][tid] = xp[(size_t)c * HW_];
    __syncthreads();

    if (tid < C_) {
        const float4* r = (const float4*)sX[tid];
        float a0 = 0.f, a1 = 0.f, a2 = 0.f, a3 = 0.f;
#pragma unroll
        for (int p = 0; p < 64; p++) {
            float4 v = r[p];
            a0 += v.x; a1 += v.y; a2 += v.z; a3 += v.w;
        }
        g_seeds[b][sidx][tid] = ((a0 + a1) + (a2 + a3)) * (1.f / 256.f);
    }
}

// ---------------------------------------------------------------------------
// Main kernel: one CTA = one (b, cell). 64 threads, thread = 4 adjacent px
// (R13 structure — proven). logit[o] = 2*x.s_o - |s_o|^2.
//
// GEMM retile (this round): 64 threads = (ALL 9 o x 5 c) x 4 cgr x 16 kq.
// Thread (cgr, kq) covers pixel ROW kq for channels 5cgr..5cgr+4:
// X read 1x (20KB, was 60KB), Q 4x (36KB). Scalar accumulators (45 regs).
// K-combine: 2-step shfl butterfly (4 slices) + 4.4KB smem stage.
// ---------------------------------------------------------------------------
template<int SRC, bool FINAL>
__global__ void __launch_bounds__(64, 10) k_main(const float* __restrict__ x,
                                                 float* __restrict__ out)
{
    __shared__ __align__(16) float sS[9][20];      // 2*seed
    __shared__ float sD0[9];                       // |seed|^2
    __shared__ int   sIdx[9];                      // clipped global seed index
    __shared__ float sDen[9];                      // warp-1 denom partials
    __shared__ float sPart[540];                   // 4 cgr x 3 groups x 45
    __shared__ __align__(16) float sQ[9][PSTRQ];   // staged Q

    const int b  = blockIdx.z, cy = blockIdx.y, cx = blockIdx.x;
    const int tid = threadIdx.x;

    // Thread's pixel quad (logits phase)
    const int ty  = tid >> 2;
    const int tx0 = (tid & 3) * 4;
    const float* xp = x + (size_t)b * C_ * HW_
                        + (size_t)(cy * CELL_ + ty) * W_ + (cx * CELL_ + tx0);
    const ulonglong2* xq = (const ulonglong2*)xp;
    const int p0 = tid * 4;

    // PREFETCH: channel group g=0 before the seed barrier
    ulonglong2 xg0[4];
#pragma unroll
    for (int j = 0; j < 4; j++) xg0[j] = xq[(size_t)j * HW4];

    // Seed tile (pre-doubled) + neighbor indices, strided over 64 threads
    for (int t = tid; t < 180; t += 64) {
        const int o = t / 20, c = t - o * 20;
        int iy = cy + c_dy[o]; iy = iy < 0 ? 0 : (iy > SH_ - 1 ? SH_ - 1 : iy);
        int ix = cx + c_dx[o]; ix = ix < 0 ? 0 : (ix > SW_ - 1 ? SW_ - 1 : ix);
        const int sidx = iy * SW_ + ix;
        if (c == 0) sIdx[o] = sidx;
        float sv;
        if (SRC == 0) {
            sv = g_seeds[b][sidx][c];
        } else {
            sv = g_numerB[SRC - 1][b][sidx][c]
               / (g_denomB[SRC - 1][b][sidx] + EPSV);
        }
        sS[o][c] = 2.f * sv;
    }
    __syncthreads();

    if (tid < 9) {
        float a = 0.f;
#pragma unroll
        for (int c = 0; c < C_; c++) a += sS[tid][c] * sS[tid][c];
        sD0[tid] = 0.25f * a;   // sS holds 2s
    }

    // Logits, packed: L01 = pixels 0,1 ; L23 = pixels 2,3
    u64 L01[9], L23[9];
#pragma unroll
    for (int o = 0; o < 9; o++) { L01[o] = 0ull; L23[o] = 0ull; }

#pragma unroll
    for (int g = 0; g < 5; g++) {
        ulonglong2 xg[4];
        if (g == 0) {
#pragma unroll
            for (int j = 0; j < 4; j++) xg[j] = xg0[j];
        } else {
#pragma unroll
            for (int j = 0; j < 4; j++)
                xg[j] = xq[(size_t)(4 * g + j) * HW4];
        }
#pragma unroll
        for (int o = 0; o < 9; o++) {
            const float4 s4 = *(const float4*)&sS[o][4 * g];
            const u64 b0 = pkdup(s4.x), b1 = pkdup(s4.y);
            const u64 b2 = pkdup(s4.z), b3 = pkdup(s4.w);
            L01[o] = fma2(xg[0].x, b0, L01[o]);
            L23[o] = fma2(xg[0].y, b0, L23[o]);
            L01[o] = fma2(xg[1].x, b1, L01[o]);
            L23[o] = fma2(xg[1].y, b1, L23[o]);
            L01[o] = fma2(xg[2].x, b2, L01[o]);
            L23[o] = fma2(xg[2].y, b2, L23[o]);
            L01[o] = fma2(xg[3].x, b3, L01[o]);
            L23[o] = fma2(xg[3].y, b3, L23[o]);
        }
    }
    __syncthreads();   // sD0 ready

    // Unpack logits, subtract |s|^2, softmax over o
    float4 L[9];
#pragma unroll
    for (int o = 0; o < 9; o++) {
        upk2(L01[o], L[o].x, L[o].y);
        upk2(L23[o], L[o].z, L[o].w);
        const float d0 = sD0[o];
        L[o].x -= d0; L[o].y -= d0; L[o].z -= d0; L[o].w -= d0;
    }
    float4 m = L[0];
#pragma unroll
    for (int o = 1; o < 9; o++) {
        m.x = fmaxf(m.x, L[o].x); m.y = fmaxf(m.y, L[o].y);
        m.z = fmaxf(m.z, L[o].z); m.w = fmaxf(m.w, L[o].w);
    }
    float4 sum = make_float4(0.f, 0.f, 0.f, 0.f);
#pragma unroll
    for (int o = 0; o < 9; o++) {
        L[o].x = __expf(L[o].x - m.x); sum.x += L[o].x;
        L[o].y = __expf(L[o].y - m.y); sum.y += L[o].y;
        L[o].z = __expf(L[o].z - m.z); sum.z += L[o].z;
        L[o].w = __expf(L[o].w - m.w); sum.w += L[o].w;
    }
    const float4 inv = make_float4(1.f / sum.x, 1.f / sum.y,
                                   1.f / sum.z, 1.f / sum.w);
#pragma unroll
    for (int o = 0; o < 9; o++) {
        L[o].x *= inv.x; L[o].y *= inv.y; L[o].z *= inv.z; L[o].w *= inv.w;
    }

    if constexpr (FINAL) {
        const int yy = cy * CELL_ + ty, xx = cx * CELL_ + tx0;
        float* op = out + (size_t)b * 9 * HW_ + (size_t)yy * W_ + xx;
#pragma unroll
        for (int o = 0; o < 9; o++) *(float4*)(op + (size_t)o * HW_) = L[o];
        return;
    } else {

    // Stage Q (cell-row-major: sQ[o][p], p = tid*4..) + denom quad sums
    float qs[9];
#pragma unroll
    for (int o = 0; o < 9; o++) {
        *(float4*)&sQ[o][p0] = L[o];
        qs[o] = (L[o].x + L[o].y) + (L[o].z + L[o].w);
    }
#pragma unroll
    for (int o = 0; o < 9; o++) {
#pragma unroll
        for (int d = 16; d >= 1; d >>= 1)
            qs[o] += __shfl_xor_sync(0xffffffffu, qs[o], d);
    }
    if (tid == 32) {
#pragma unroll
        for (int o = 0; o < 9; o++) sDen[o] = qs[o];
    }

    // GEMM setup: thread (cgr = tid>>4, kq = tid&15) owns pixel row kq,
    // channels 5cgr..5cgr+4. Prefetch i=0 chunks before the Q barrier.
    const int cgr = tid >> 4, kq = tid & 15;
    const float4* px[5];
    float4 xpre[5];
    {
        const float* xrow = x + (size_t)b * C_ * HW_
                              + (size_t)(cy * CELL_ + kq) * W_ + cx * CELL_;
#pragma unroll
        for (int jc = 0; jc < 5; jc++) {
            px[jc] = (const float4*)(xrow + (size_t)(5 * cgr + jc) * HW_);
            xpre[jc] = px[jc][0];
        }
    }
    __syncthreads();   // Q staged + sDen ready

    if (tid == 0) {
#pragma unroll
        for (int o = 0; o < 9; o++)
            atomicAdd(&g_denomB[SRC][b][sIdx[o]], qs[o] + sDen[o]);
    }

    // Reduction GEMM: all 9 offsets x 5 channels over this thread's row.
    // Scalar accumulators (45 regs), X chunks held across all 9 offsets.
    float acc[9][5];
#pragma unroll
    for (int jo = 0; jo < 9; jo++)
#pragma unroll
        for (int jc = 0; jc < 5; jc++) acc[jo][jc] = 0.f;

#pragma unroll
    for (int i = 0; i < 4; i++) {
        float4 xc[5];
#pragma unroll
        for (int jc = 0; jc < 5; jc++)
            xc[jc] = (i == 0) ? xpre[jc] : px[jc][i];
        const int ck = 4 * kq + i;          // Q chunk = row kq, quad i
#pragma unroll
        for (int jo = 0; jo < 9; jo++) {
            const float4 qv = ((const float4*)&sQ[jo][0])[ck];
#pragma unroll
            for (int jc = 0; jc < 5; jc++) {
                acc[jo][jc] = fmaf(xc[jc].x, qv.x, acc[jo][jc]);
                acc[jo][jc] = fmaf(xc[jc].y, qv.y, acc[jo][jc]);
                acc[jo][jc] = fmaf(xc[jc].z, qv.z, acc[jo][jc]);
                acc[jo][jc] = fmaf(xc[jc].w, qv.w, acc[jo][jc]);
            }
        }
    }

    // K-combine stage 1: butterfly over kq bits 0,1 (lane bits 0,1 — same
    // cgr group). After this, lanes with kq%4==0 hold their 4-row-group sum.
#pragma unroll
    for (int jo = 0; jo < 9; jo++)
#pragma unroll
        for (int jc = 0; jc < 5; jc++) {
            float v = acc[jo][jc];
            v += __shfl_xor_sync(0xffffffffu, v, 1);
            v += __shfl_xor_sync(0xffffffffu, v, 2);
            acc[jo][jc] = v;
        }

    // Stage 2: groups g = kq>>2; g>0 reps stage 45 floats, g==0 combines.
    const int g4 = kq >> 2;
    if ((kq & 3) == 0 && g4 > 0) {
        float* dst = &sPart[(cgr * 3 + (g4 - 1)) * 45];
#pragma unroll
        for (int jo = 0; jo < 9; jo++)
#pragma unroll
            for (int jc = 0; jc < 5; jc++) dst[jo * 5 + jc] = acc[jo][jc];
    }
    __syncthreads();   // unconditional

    if (kq == 0) {
#pragma unroll
        for (int p = 0; p < 3; p++) {
            const float* src = &sPart[(cgr * 3 + p) * 45];
#pragma unroll
            for (int jo = 0; jo < 9; jo++)
#pragma unroll
                for (int jc = 0; jc < 5; jc++) acc[jo][jc] += src[jo * 5 + jc];
        }
#pragma unroll
        for (int jo = 0; jo < 9; jo++) {
            const int sidx = sIdx[jo];
#pragma unroll
            for (int jc = 0; jc < 5; jc++)
                atomicAdd(&g_numerB[SRC][b][sidx][5 * cgr + jc], acc[jo][jc]);
        }
    }
    }  // !FINAL
}

// ---------------------------------------------------------------------------
extern "C" void kernel_launch(void* const* d_in, const int* in_sizes, int n_in,
                              void* d_out, int out_size)
{
    const float* x = (const float*)d_in[0];
    float* out = (float*)d_out;

    dim3 grid(SW_, SH_, B_);

    k_init<<<grid, 256>>>(x);
    k_main<0, false><<<grid, 64>>>(x, nullptr);   // seeds=means  -> buf0
    k_main<1, false><<<grid, 64>>>(x, nullptr);   // seeds=buf0   -> buf1
    k_main<2, false><<<grid, 64>>>(x, nullptr);   // seeds=buf1   -> buf2
    k_main<3, true ><<<grid, 64>>>(x, out);       // seeds=buf2   -> output
}

// round 16
// speedup vs baseline: 1.5753x; 1.5753x over previous
#include <cuda_runtime.h>

#define B_    8
#define C_    20
#define H_    512
#define W_    512
#define SH_   32
#define SW_   32
#define S_    1024
#define CELL_ 16
#define HW_   (H_*W_)
#define HW4   (HW_/4)
#define PSTR  260
#define PSTRQ 264            // Q staging stride (floats): 66 16B-chunks
#define EPSV  1e-8f

typedef unsigned long long u64;

// Packed fp32x2 helpers (SASS FFMA2 — PTX-only)
__device__ __forceinline__ u64 pkdup(float s) {
    u64 r; asm("mov.b64 %0,{%1,%1};" : "=l"(r) : "f"(s)); return r;
}
__device__ __forceinline__ void upk2(u64 v, float& lo, float& hi) {
    asm("mov.b64 {%0,%1},%2;" : "=f"(lo), "=f"(hi) : "l"(v));
}
__device__ __forceinline__ u64 fma2(u64 a, u64 b, u64 c) {
    u64 d; asm("fma.rn.f32x2 %0,%1,%2,%3;" : "=l"(d) : "l"(a), "l"(b), "l"(c));
    return d;
}

__device__ float g_seeds[B_][S_][C_];          // iteration-0 seeds (means)
__device__ float g_numerB[3][B_][S_][C_];      // per-iteration accumulators
__device__ float g_denomB[3][B_][S_];

__constant__ int c_dy[9] = {-1,-1,-1, 0,0,0, 1,1,1};
__constant__ int c_dx[9] = {-1, 0, 1,-1,0,1,-1,0,1};

// ---------------------------------------------------------------------------
// K0: seed init = 16x16 mean pool per (b, cell, c); zero ALL 3 accumulator
// buffers (seed division is fused into k_main's seed loader).
// ---------------------------------------------------------------------------
__global__ void __launch_bounds__(256) k_init(const float* __restrict__ x)
{
    __shared__ __align__(16) float sX[C_][PSTR];
    const int b  = blockIdx.z, cy = blockIdx.y, cx = blockIdx.x;
    const int tid = threadIdx.x;
    const int ty = tid >> 4, tx = tid & 15;
    const int sidx = cy * SW_ + cx;

    if (tid < 63) {
        const int buf = tid / 21, c = tid % 21;
        if (c < 20) g_numerB[buf][b][sidx][c] = 0.f;
        else        g_denomB[buf][b][sidx]    = 0.f;
    }

    const float* xp = x + (size_t)b * C_ * HW_
                        + (size_t)(cy * CELL_ + ty) * W_ + (cx * CELL_ + tx);
#pragma unroll
    for (int c = 0; c < C_; c++) sX[c][tid] = xp[(size_t)c * HW_];
    __syncthreads();

    if (tid < C_) {
        const float4* r = (const float4*)sX[tid];
        float a0 = 0.f, a1 = 0.f, a2 = 0.f, a3 = 0.f;
#pragma unroll
        for (int p = 0; p < 64; p++) {
            float4 v = r[p];
            a0 += v.x; a1 += v.y; a2 += v.z; a3 += v.w;
        }
        g_seeds[b][sidx][tid] = ((a0 + a1) + (a2 + a3)) * (1.f / 256.f);
    }
}

// ---------------------------------------------------------------------------
// Main kernel: one CTA = one (b, cell). 64 threads, thread = 4 adjacent px
// (logits; R13-proven). logit[o] = 2*x.s_o - |s_o|^2.
//
// GEMM: 64 threads = (ALL 9 o x 5 c) x 4 cgr x 16 kq.
// Thread (cgr, kq) owns chunks ck = kq + 16*i  (i = 0..3):
//   -> Q LDS: 16 lanes read 16 CONSECUTIVE chunks -> conflict-free
//      (R15's ck = 4kq+i had stride-4 chunks -> 8-way conflict, the bug)
//   -> X: row (kq>>2)+4i, col-quad kq&3 (fixed) -> X read 1x (20KB vs 60KB)
//   -> K-combine: pure shfl butterfly within each 16-lane group; no sPart,
//      no trailing barrier.
// ---------------------------------------------------------------------------
template<int SRC, bool FINAL>
__global__ void __launch_bounds__(64, 10) k_main(const float* __restrict__ x,
                                                 float* __restrict__ out)
{
    __shared__ __align__(16) float sS[9][20];      // 2*seed
    __shared__ float sD0[9];                       // |seed|^2
    __shared__ int   sIdx[9];                      // clipped global seed index
    __shared__ float sDen[9];                      // warp-1 denom partials
    __shared__ __align__(16) float sQ[9][PSTRQ];   // staged Q

    const int b  = blockIdx.z, cy = blockIdx.y, cx = blockIdx.x;
    const int tid = threadIdx.x;

    // Thread's pixel quad (logits phase)
    const int ty  = tid >> 2;
    const int tx0 = (tid & 3) * 4;
    const float* xp = x + (size_t)b * C_ * HW_
                        + (size_t)(cy * CELL_ + ty) * W_ + (cx * CELL_ + tx0);
    const ulonglong2* xq = (const ulonglong2*)xp;
    const int p0 = tid * 4;

    // PREFETCH: channel group g=0 before the seed barrier
    ulonglong2 xg0[4];
#pragma unroll
    for (int j = 0; j < 4; j++) xg0[j] = xq[(size_t)j * HW4];

    // Seed tile (pre-doubled) + neighbor indices, strided over 64 threads
    for (int t = tid; t < 180; t += 64) {
        const int o = t / 20, c = t - o * 20;
        int iy = cy + c_dy[o]; iy = iy < 0 ? 0 : (iy > SH_ - 1 ? SH_ - 1 : iy);
        int ix = cx + c_dx[o]; ix = ix < 0 ? 0 : (ix > SW_ - 1 ? SW_ - 1 : ix);
        const int sidx = iy * SW_ + ix;
        if (c == 0) sIdx[o] = sidx;
        float sv;
        if (SRC == 0) {
            sv = g_seeds[b][sidx][c];
        } else {
            sv = g_numerB[SRC - 1][b][sidx][c]
               / (g_denomB[SRC - 1][b][sidx] + EPSV);
        }
        sS[o][c] = 2.f * sv;
    }
    __syncthreads();

    if (tid < 9) {
        float a = 0.f;
#pragma unroll
        for (int c = 0; c < C_; c++) a += sS[tid][c] * sS[tid][c];
        sD0[tid] = 0.25f * a;   // sS holds 2s
    }

    // Logits, packed: L01 = pixels 0,1 ; L23 = pixels 2,3
    u64 L01[9], L23[9];
#pragma unroll
    for (int o = 0; o < 9; o++) { L01[o] = 0ull; L23[o] = 0ull; }

#pragma unroll
    for (int g = 0; g < 5; g++) {
        ulonglong2 xg[4];
        if (g == 0) {
#pragma unroll
            for (int j = 0; j < 4; j++) xg[j] = xg0[j];
        } else {
#pragma unroll
            for (int j = 0; j < 4; j++)
                xg[j] = xq[(size_t)(4 * g + j) * HW4];
        }
#pragma unroll
        for (int o = 0; o < 9; o++) {
            const float4 s4 = *(const float4*)&sS[o][4 * g];
            const u64 b0 = pkdup(s4.x), b1 = pkdup(s4.y);
            const u64 b2 = pkdup(s4.z), b3 = pkdup(s4.w);
            L01[o] = fma2(xg[0].x, b0, L01[o]);
            L23[o] = fma2(xg[0].y, b0, L23[o]);
            L01[o] = fma2(xg[1].x, b1, L01[o]);
            L23[o] = fma2(xg[1].y, b1, L23[o]);
            L01[o] = fma2(xg[2].x, b2, L01[o]);
            L23[o] = fma2(xg[2].y, b2, L23[o]);
            L01[o] = fma2(xg[3].x, b3, L01[o]);
            L23[o] = fma2(xg[3].y, b3, L23[o]);
        }
    }
    __syncthreads();   // sD0 ready

    // Unpack logits, subtract |s|^2, softmax over o
    float4 L[9];
#pragma unroll
    for (int o = 0; o < 9; o++) {
        upk2(L01[o], L[o].x, L[o].y);
        upk2(L23[o], L[o].z, L[o].w);
        const float d0 = sD0[o];
        L[o].x -= d0; L[o].y -= d0; L[o].z -= d0; L[o].w -= d0;
    }
    float4 m = L[0];
#pragma unroll
    for (int o = 1; o < 9; o++) {
        m.x = fmaxf(m.x, L[o].x); m.y = fmaxf(m.y, L[o].y);
        m.z = fmaxf(m.z, L[o].z); m.w = fmaxf(m.w, L[o].w);
    }
    float4 sum = make_float4(0.f, 0.f, 0.f, 0.f);
#pragma unroll
    for (int o = 0; o < 9; o++) {
        L[o].x = __expf(L[o].x - m.x); sum.x += L[o].x;
        L[o].y = __expf(L[o].y - m.y); sum.y += L[o].y;
        L[o].z = __expf(L[o].z - m.z); sum.z += L[o].z;
        L[o].w = __expf(L[o].w - m.w); sum.w += L[o].w;
    }
    const float4 inv = make_float4(1.f / sum.x, 1.f / sum.y,
                                   1.f / sum.z, 1.f / sum.w);
#pragma unroll
    for (int o = 0; o < 9; o++) {
        L[o].x *= inv.x; L[o].y *= inv.y; L[o].z *= inv.z; L[o].w *= inv.w;
    }

    if constexpr (FINAL) {
        const int yy = cy * CELL_ + ty, xx = cx * CELL_ + tx0;
        float* op = out + (size_t)b * 9 * HW_ + (size_t)yy * W_ + xx;
#pragma unroll
        for (int o = 0; o < 9; o++) *(float4*)(op + (size_t)o * HW_) = L[o];
        return;
    } else {

    // Stage Q (thread tid -> chunk tid) + denom quad sums
    float qs[9];
#pragma unroll
    for (int o = 0; o < 9; o++) {
        *(float4*)&sQ[o][p0] = L[o];
        qs[o] = (L[o].x + L[o].y) + (L[o].z + L[o].w);
    }
#pragma unroll
    for (int o = 0; o < 9; o++) {
#pragma unroll
        for (int d = 16; d >= 1; d >>= 1)
            qs[o] += __shfl_xor_sync(0xffffffffu, qs[o], d);
    }
    if (tid == 32) {
#pragma unroll
        for (int o = 0; o < 9; o++) sDen[o] = qs[o];
    }

    // GEMM setup: thread (cgr = tid>>4, kq = tid&15).
    // Chunks ck = kq + 16*i -> X row (kq>>2)+4i, col-quad kq&3 (fixed).
    const int cgr = tid >> 4, kq = tid & 15;
    const float4* px[5];
    float4 xpre[5];
    {
        const float* xrow = x + (size_t)b * C_ * HW_
                              + (size_t)(cy * CELL_ + (kq >> 2)) * W_
                              + cx * CELL_ + (kq & 3) * 4;
#pragma unroll
        for (int jc = 0; jc < 5; jc++) {
            px[jc] = (const float4*)(xrow + (size_t)(5 * cgr + jc) * HW_);
            xpre[jc] = px[jc][0];              // i=0 prefetch
        }
    }
    __syncthreads();   // Q staged + sDen ready

    if (tid == 0) {
#pragma unroll
        for (int o = 0; o < 9; o++)
            atomicAdd(&g_denomB[SRC][b][sIdx[o]], qs[o] + sDen[o]);
    }

    // Reduction GEMM: all 9 offsets x 5 channels over this thread's 4 chunks.
    // Scalar accumulators (45), X chunk held across all 9 offsets.
    float acc[9][5];
#pragma unroll
    for (int jo = 0; jo < 9; jo++)
#pragma unroll
        for (int jc = 0; jc < 5; jc++) acc[jo][jc] = 0.f;

#pragma unroll
    for (int i = 0; i < 4; i++) {
        float4 xc[5];
#pragma unroll
        for (int jc = 0; jc < 5; jc++)
            xc[jc] = (i == 0) ? xpre[jc] : px[jc][(size_t)i * W_];  // +4 rows = W_ float4s
        const int ck = kq + 16 * i;
#pragma unroll
        for (int jo = 0; jo < 9; jo++) {
            const float4 qv = ((const float4*)&sQ[jo][0])[ck];
#pragma unroll
            for (int jc = 0; jc < 5; jc++) {
                acc[jo][jc] = fmaf(xc[jc].x, qv.x, acc[jo][jc]);
                acc[jo][jc] = fmaf(xc[jc].y, qv.y, acc[jo][jc]);
                acc[jo][jc] = fmaf(xc[jc].z, qv.z, acc[jo][jc]);
                acc[jo][jc] = fmaf(xc[jc].w, qv.w, acc[jo][jc]);
            }
        }
    }

    // K-combine: full butterfly over the 16-lane group (xor 1,2,4,8 stay
    // inside the group). Lane kq==0 of each cgr group holds the total.
#pragma unroll
    for (int jo = 0; jo < 9; jo++)
#pragma unroll
        for (int jc = 0; jc < 5; jc++) {
            float v = acc[jo][jc];
            v += __shfl_xor_sync(0xffffffffu, v, 1);
            v += __shfl_xor_sync(0xffffffffu, v, 2);
            v += __shfl_xor_sync(0xffffffffu, v, 4);
            v += __shfl_xor_sync(0xffffffffu, v, 8);
            acc[jo][jc] = v;
        }

    if (kq == 0) {
#pragma unroll
        for (int jo = 0; jo < 9; jo++) {
            const int sidx = sIdx[jo];
#pragma unroll
            for (int jc = 0; jc < 5; jc++)
                atomicAdd(&g_numerB[SRC][b][sidx][5 * cgr + jc], acc[jo][jc]);
        }
    }
    }  // !FINAL
}

// ---------------------------------------------------------------------------
extern "C" void kernel_launch(void* const* d_in, const int* in_sizes, int n_in,
                              void* d_out, int out_size)
{
    const float* x = (const float*)d_in[0];
    float* out = (float*)d_out;

    dim3 grid(SW_, SH_, B_);

    k_init<<<grid, 256>>>(x);
    k_main<0, false><<<grid, 64>>>(x, nullptr);   // seeds=means  -> buf0
    k_main<1, false><<<grid, 64>>>(x, nullptr);   // seeds=buf0   -> buf1
    k_main<2, false><<<grid, 64>>>(x, nullptr);   // seeds=buf1   -> buf2
    k_main<3, true ><<<grid, 64>>>(x, out);       // seeds=buf2   -> output
}